// round 7
// baseline (speedup 1.0000x reference)
#include <cuda_runtime.h>
#include <cuda_bf16.h>
#include <math.h>
#include <stdint.h>

#define N 8192
#define D 128
#define NC 512
#define MAXM 64

// ---------------- scratch (device globals; no allocation allowed) ----------
__device__ __align__(16) float g_enorm[N * D];
__device__ __align__(16) __nv_bfloat16 g_hi[N * D];
__device__ __align__(16) __nv_bfloat16 g_mid[N * D];
__device__ int   g_cnt[NC];
__device__ int   g_members[NC * MAXM];
__device__ float g_lsep[N];
__device__ float g_samesum[N];
__device__ float g_sall[N];
__device__ float g_part[32];
__device__ int   g_pcnt[32];
__device__ int   g_is64;

__device__ __forceinline__ float an_exp(float s) {
    float t = fmaxf(s + 0.4f, 0.0f);
    return __expf(80.0f * t * (s - 0.4f));
}

__device__ __forceinline__ int get_label(const void* lab, int i) {
    if (g_is64) return (int)((const long long*)lab)[i];
    return ((const int*)lab)[i];
}

__device__ __forceinline__ uint32_t smem_u32(const void* p) {
    uint32_t a;
    asm("{ .reg .u64 t; cvta.to.shared.u64 t, %1; cvt.u32.u64 %0, t; }" : "=r"(a) : "l"(p));
    return a;
}
__device__ __forceinline__ void cpa16(uint32_t dst, const void* src) {
    asm volatile("cp.async.cg.shared.global [%0], [%1], 16;" :: "r"(dst), "l"(src) : "memory");
}
__device__ __forceinline__ void ldsm4(uint32_t* r, uint32_t addr) {
    asm volatile("ldmatrix.sync.aligned.m8n8.x4.shared.b16 {%0,%1,%2,%3}, [%4];"
        : "=r"(r[0]), "=r"(r[1]), "=r"(r[2]), "=r"(r[3]) : "r"(addr));
}
__device__ __forceinline__ void mma_bf16(float* d, const uint32_t* a, uint32_t b0, uint32_t b1) {
    asm volatile(
        "mma.sync.aligned.m16n8k16.row.col.f32.bf16.bf16.f32 "
        "{%0,%1,%2,%3}, {%4,%5,%6,%7}, {%8,%9}, {%0,%1,%2,%3};\n"
        : "+f"(d[0]), "+f"(d[1]), "+f"(d[2]), "+f"(d[3])
        : "r"(a[0]), "r"(a[1]), "r"(a[2]), "r"(a[3]), "r"(b0), "r"(b1));
}

// ---------------- kernel 0: tiny pre (g_cnt zero + dtype flag) -------------
__global__ void k_pre(const void* lab) {
    int i = blockIdx.x * blockDim.x + threadIdx.x;
    if (i < NC) g_cnt[i] = 0;
    if (i == 0) {
        const int* w = (const int*)lab;
        int bad = 0;
        #pragma unroll
        for (int k = 1; k < 128; k += 2) bad |= w[k];
        g_is64 = (bad == 0);
    }
}

// ---------------- kernel 1: normalize + bf16 split + lists + zero sall -----
__global__ void k_norm(const float* __restrict__ in, const void* __restrict__ lab) {
    int gid = blockIdx.x * blockDim.x + threadIdx.x;
    if (gid < N) g_sall[gid] = 0.0f;
    int row  = blockIdx.x * 8 + (threadIdx.x >> 5);
    int lane = threadIdx.x & 31;
    float4 v = *(const float4*)(in + row * D + lane * 4);
    float ss = v.x * v.x + v.y * v.y + v.z * v.z + v.w * v.w;
    #pragma unroll
    for (int m = 16; m >= 1; m >>= 1) ss += __shfl_xor_sync(0xffffffffu, ss, m);
    float inv = 1.0f / fmaxf(sqrtf(ss), 1e-12f);
    float o[4] = {v.x * inv, v.y * inv, v.z * inv, v.w * inv};
    float4 of; of.x = o[0]; of.y = o[1]; of.z = o[2]; of.w = o[3];
    *(float4*)(g_enorm + row * D + lane * 4) = of;
    #pragma unroll
    for (int c = 0; c < 4; c++) {
        __nv_bfloat16 h = __float2bfloat16(o[c]);
        float r = o[c] - __bfloat162float(h);
        g_hi [row * D + lane * 4 + c] = h;
        g_mid[row * D + lane * 4 + c] = __float2bfloat16(r);
    }
    if (lane == 0) {
        int c = get_label(lab, row);
        int p = atomicAdd(&g_cnt[c], 1);
        if (p < MAXM) g_members[c * MAXM + p] = row;
    }
}

// ---------------- kernel 2: per-class positives, warp-per-anchor -----------
__global__ void k_class() {
    int c = blockIdx.x;
    __shared__ int   mlist[MAXM];
    __shared__ float se[MAXM * 129];
    int m = g_cnt[c];
    if (m > MAXM) m = MAXM;
    if (m == 0) return;
    int tid = threadIdx.x, lane = tid & 31, wid = tid >> 5;
    if (tid < m) mlist[tid] = g_members[c * MAXM + tid];
    __syncthreads();
    for (int p = tid; p < m * D; p += blockDim.x) {
        int r = p >> 7, k = p & 127;
        se[r * 129 + k] = g_enorm[mlist[r] * D + k];
    }
    __syncthreads();
    for (int a = wid; a < m; a += 4) {
        int b0 = lane, b1 = lane + 32;
        float s0 = 0.0f, s1 = 0.0f;
        const float* ra = se + a * 129;
        #pragma unroll 8
        for (int k = 0; k < D; k++) {
            float av = ra[k];
            s0 = fmaf(av, se[b0 * 129 + k], s0);
            s1 = fmaf(av, se[b1 * 129 + k], s1);
        }
        float ap0 = -1e30f, ap1 = -1e30f, an0 = 0.0f, an1 = 0.0f;
        bool v0 = (b0 < m && b0 != a), v1 = (b1 < m && b1 != a);
        if (v0) { ap0 = -80.0f * fmaxf(1.4f - s0, 0.0f) * (s0 - 0.6f); an0 = an_exp(s0); }
        if (v1) { ap1 = -80.0f * fmaxf(1.4f - s1, 0.0f) * (s1 - 0.6f); an1 = an_exp(s1); }
        float mx = fmaxf(ap0, ap1);
        #pragma unroll
        for (int k = 16; k >= 1; k >>= 1) mx = fmaxf(mx, __shfl_xor_sync(0xffffffffu, mx, k));
        float es = (v0 ? __expf(ap0 - mx) : 0.0f) + (v1 ? __expf(ap1 - mx) : 0.0f);
        float sa = an0 + an1;
        #pragma unroll
        for (int k = 16; k >= 1; k >>= 1) {
            es += __shfl_xor_sync(0xffffffffu, es, k);
            sa += __shfl_xor_sync(0xffffffffu, sa, k);
        }
        if (lane == 0) {
            g_lsep[mlist[a]]    = mx + logf(es);
            g_samesum[mlist[a]] = sa;
        }
    }
}

// ---------------- kernel 3: mma.sync, rolling 4-deep cp.async pipeline -----
// smem layout IDENTICAL to R4/R6 (proven): 4 arrays x 128 rows x 64 halves,
// row stride 144B. K chunks of 16 (32B/row) are the pipeline granule:
// global group g (0..7): phase kc = g>>2, slot = g&3 (byte offset (g&3)*32).
#define SROW   144
#define SA_HI  0
#define SA_MID (128 * SROW)
#define SB_HI  (2 * 128 * SROW)
#define SB_MID (3 * 128 * SROW)
#define SMEM_SZ (4 * 128 * SROW)   // 73728 B

__global__ void __launch_bounds__(256, 2) k_main_m() {
    int b = blockIdx.x;
    int r = (int)((__fsqrt_rn(8.0f * (float)b + 1.0f) - 1.0f) * 0.5f);
    while ((r + 1) * (r + 2) / 2 <= b) r++;
    while (r * (r + 1) / 2 > b) r--;
    int bi = b - r * (r + 1) / 2;
    int bj = r;

    extern __shared__ char sm[];
    uint32_t sb = smem_u32(sm);
    int tid = threadIdx.x;
    int lane = tid & 31, wid = tid >> 5;
    int g = lane >> 2, t = lane & 3;
    int wm = wid & 3, wn = wid >> 2;
    int rowBase = bi * 128, colBase = bj * 128;

    // per-thread cp.async slot: row = tid>>1, h = tid&1 (which 16B of the 32B)
    int ldRow = tid >> 1, ldH = tid & 1;
    uint32_t ldSo = (uint32_t)(ldRow * SROW + ldH * 16);
    size_t ldA = (size_t)(rowBase + ldRow) * 16 + ldH;
    size_t ldB = (size_t)(colBase + ldRow) * 16 + ldH;

    uint32_t lmo = (uint32_t)((lane & 15) * SROW + (lane >> 4) * 16);
    uint32_t aBaseHi  = sb + SA_HI  + (uint32_t)(wm * 32) * SROW + lmo;
    uint32_t aBaseMid = sb + SA_MID + (uint32_t)(wm * 32) * SROW + lmo;
    uint32_t bBaseHi  = sb + SB_HI  + (uint32_t)(wn * 64) * SROW + lmo;
    uint32_t bBaseMid = sb + SB_MID + (uint32_t)(wn * 64) * SROW + lmo;

    float acc[2][8][4];
    #pragma unroll
    for (int i = 0; i < 2; i++)
        #pragma unroll
        for (int j = 0; j < 8; j++)
            #pragma unroll
            for (int e = 0; e < 4; e++) acc[i][j][e] = 0.0f;

    // issue_group(gg): 4 cp.async + commit
    #define ISSUE_GROUP(gg) do {                                                  \
        uint32_t _so = ldSo + (uint32_t)(((gg) & 3) * 32);                        \
        size_t _ko = (size_t)(((gg) >> 2) * 8 + ((gg) & 3) * 2);                  \
        cpa16(sb + SA_HI  + _so, (const uint4*)g_hi  + ldA + _ko);                \
        cpa16(sb + SA_MID + _so, (const uint4*)g_mid + ldA + _ko);                \
        cpa16(sb + SB_HI  + _so, (const uint4*)g_hi  + ldB + _ko);                \
        cpa16(sb + SB_MID + _so, (const uint4*)g_mid + ldB + _ko);                \
        asm volatile("cp.async.commit_group;" ::: "memory");                      \
    } while (0)

    // prologue: groups 0..3 in flight
    ISSUE_GROUP(0); ISSUE_GROUP(1); ISSUE_GROUP(2); ISSUE_GROUP(3);

    #pragma unroll
    for (int gg = 0; gg < 8; gg++) {
        // wait for group gg: outstanding allowed = min(3, 7-gg)
        if (gg <= 4)      asm volatile("cp.async.wait_group 3;" ::: "memory");
        else if (gg == 5) asm volatile("cp.async.wait_group 2;" ::: "memory");
        else if (gg == 6) asm volatile("cp.async.wait_group 1;" ::: "memory");
        else              asm volatile("cp.async.wait_group 0;" ::: "memory");
        __syncthreads();

        uint32_t ko = (uint32_t)((gg & 3) * 32);
        uint32_t ah[2][4], am[2][4];
        ldsm4(ah[0], aBaseHi  + ko);
        ldsm4(ah[1], aBaseHi  + ko + 16 * SROW);
        ldsm4(am[0], aBaseMid + ko);
        ldsm4(am[1], aBaseMid + ko + 16 * SROW);
        #pragma unroll
        for (int jp = 0; jp < 4; jp++) {
            uint32_t bh[4], bm[4];
            ldsm4(bh, bBaseHi  + ko + (uint32_t)(jp * 16) * SROW);
            ldsm4(bm, bBaseMid + ko + (uint32_t)(jp * 16) * SROW);
            // same-acc MMAs spaced 4 apart (4 independent accumulators cycling)
            mma_bf16(acc[0][2 * jp],     ah[0], bh[0], bh[2]);
            mma_bf16(acc[1][2 * jp],     ah[1], bh[0], bh[2]);
            mma_bf16(acc[0][2 * jp + 1], ah[0], bh[1], bh[3]);
            mma_bf16(acc[1][2 * jp + 1], ah[1], bh[1], bh[3]);
            mma_bf16(acc[0][2 * jp],     am[0], bh[0], bh[2]);
            mma_bf16(acc[1][2 * jp],     am[1], bh[0], bh[2]);
            mma_bf16(acc[0][2 * jp + 1], am[0], bh[1], bh[3]);
            mma_bf16(acc[1][2 * jp + 1], am[1], bh[1], bh[3]);
            mma_bf16(acc[0][2 * jp],     ah[0], bm[0], bm[2]);
            mma_bf16(acc[1][2 * jp],     ah[1], bm[0], bm[2]);
            mma_bf16(acc[0][2 * jp + 1], ah[0], bm[1], bm[3]);
            mma_bf16(acc[1][2 * jp + 1], ah[1], bm[1], bm[3]);
        }

        if (gg < 4) {
            __syncthreads();           // slot (gg&3) fully consumed by all warps
            ISSUE_GROUP(gg + 4);
        }
    }
    #undef ISSUE_GROUP

    bool diag = (bi == bj);
    #pragma unroll
    for (int i = 0; i < 2; i++)
        #pragma unroll
        for (int j = 0; j < 8; j++)
            #pragma unroll
            for (int e = 0; e < 4; e++) {
                float x = an_exp(acc[i][j][e]);
                if (diag) {
                    int rl = wm * 32 + i * 16 + g + ((e >> 1) << 3);
                    int cl = wn * 64 + j * 8 + 2 * t + (e & 1);
                    if (rl == cl) x = 0.0f;
                }
                acc[i][j][e] = x;
            }
    #pragma unroll
    for (int i = 0; i < 2; i++)
        #pragma unroll
        for (int h = 0; h < 2; h++) {
            float v = 0.0f;
            #pragma unroll
            for (int j = 0; j < 8; j++) v += acc[i][j][2 * h] + acc[i][j][2 * h + 1];
            v += __shfl_xor_sync(0xffffffffu, v, 1);
            v += __shfl_xor_sync(0xffffffffu, v, 2);
            if (t == 0)
                atomicAdd(&g_sall[rowBase + wm * 32 + i * 16 + g + h * 8], v);
        }
    if (!diag) {
        #pragma unroll
        for (int j = 0; j < 8; j++)
            #pragma unroll
            for (int bb = 0; bb < 2; bb++) {
                float v = acc[0][j][bb] + acc[0][j][2 + bb] +
                          acc[1][j][bb] + acc[1][j][2 + bb];
                v += __shfl_xor_sync(0xffffffffu, v, 4);
                v += __shfl_xor_sync(0xffffffffu, v, 8);
                v += __shfl_xor_sync(0xffffffffu, v, 16);
                if (g == 0)
                    atomicAdd(&g_sall[colBase + wn * 64 + j * 8 + 2 * t + bb], v);
            }
    }
}

// ---------------- kernel 4a: parallel finalize (one anchor per thread) -----
__global__ void k_finalp(const void* __restrict__ lab) {
    __shared__ float ssum[256];
    __shared__ int   scnt[256];
    int tid = threadIdx.x;
    int i = blockIdx.x * 256 + tid;
    int c = get_label(lab, i);
    int m = g_cnt[c];
    int np = m - 1, nn = N - m;
    float sp = 0.0f;
    int ok = 0;
    if (np > 0 && nn > 0) {
        float sneg = g_sall[i] - g_samesum[i];
        sneg = fmaxf(sneg, 1e-30f);
        float x = g_lsep[i] + logf((float)nn) + logf(sneg) + logf((float)np);
        sp = (x > 0.0f) ? (x + log1pf(__expf(-x))) : log1pf(__expf(x));
        ok = 1;
    }
    ssum[tid] = sp; scnt[tid] = ok;
    __syncthreads();
    #pragma unroll
    for (int s = 128; s > 0; s >>= 1) {
        if (tid < s) { ssum[tid] += ssum[tid + s]; scnt[tid] += scnt[tid + s]; }
        __syncthreads();
    }
    if (tid == 0) { g_part[blockIdx.x] = ssum[0]; g_pcnt[blockIdx.x] = scnt[0]; }
}

// ---------------- kernel 4b: deterministic 32-way reduce -------------------
__global__ void k_final2(float* __restrict__ out) {
    int lane = threadIdx.x;
    float v = g_part[lane];
    int   c = g_pcnt[lane];
    #pragma unroll
    for (int k = 16; k >= 1; k >>= 1) {
        v += __shfl_xor_sync(0xffffffffu, v, k);
        c += __shfl_xor_sync(0xffffffffu, c, k);
    }
    if (lane == 0) out[0] = v / fmaxf((float)c, 1.0f);
}

// ---------------- launch ---------------------------------------------------
extern "C" void kernel_launch(void* const* d_in, const int* in_sizes, int n_in,
                              void* d_out, int out_size) {
    const float* embeds = (const float*)d_in[0];
    const void*  labels = d_in[1];
    float* out = (float*)d_out;
    (void)in_sizes; (void)n_in; (void)out_size;

    cudaFuncSetAttribute(k_main_m, cudaFuncAttributeMaxDynamicSharedMemorySize, SMEM_SZ);

    k_pre<<<2, 256>>>(labels);
    k_norm<<<N / 8, 256>>>(embeds, labels);
    k_class<<<NC, 128>>>();
    k_main_m<<<2080, 256, SMEM_SZ>>>();
    k_finalp<<<32, 256>>>(labels);
    k_final2<<<1, 32>>>(out);
}